// round 13
// baseline (speedup 1.0000x reference)
#include <cuda_runtime.h>
#include <cuda_fp16.h>
#include <stdint.h>

#define N_NODES     50000
#define IN_DIM      128
#define N_EDGES     500000
#define EDGE_UNITS  (N_EDGES / 2)          // 250000 int2-edge units
#define NG4         (N_NODES / 4)          // 12500 groups of 4 nodes
#define THREADS     1024
#define MAX_SLOTS   3                      // grid>=82 -> 3 slots cover EDGE_UNITS
#define TABLE_BYTES (N_NODES * 4)          // 200000 B of half2 pairs
#define CHUNK_BYTES (TABLE_BYTES / 2)      // 100000 B per cluster rank (16B mult.)

__device__ __half2  g_pair[N_NODES];
__device__ unsigned g_cnt = 0;             // barrier arrivals (self-resets)
__device__ unsigned g_gen = 0;             // barrier generation (monotonic)

__device__ __forceinline__ float sigmoid_tanh(float v) {
    float t;
    asm("tanh.approx.f32 %0, %1;" : "=f"(t) : "f"(0.5f * v));
    return fmaf(0.5f, t, 0.5f);
}

// ---------------------------------------------------------------------------
// ONE persistent kernel: proj -> grid barrier -> multicast table staging ->
// smem gathers. 1 CTA/SM (195KB smem), cluster 2 for staging dedup.
// ---------------------------------------------------------------------------
__global__ __launch_bounds__(THREADS, 1) __cluster_dims__(2, 1, 1)
void fused_kernel(const float* __restrict__ x,
                  const int*   __restrict__ edge_index,
                  const float* __restrict__ edge_weight,
                  const float* __restrict__ W,
                  const float* __restrict__ b,
                  float*       __restrict__ out) {
    extern __shared__ __half2 s_tab[];           // 195.3 KB table
    __shared__ __align__(8) uint64_t s_mbar;

    const int tid  = threadIdx.x;
    const int wid  = tid >> 5;
    const int lane = tid & 31;
    const uint32_t mbar_a = (uint32_t)__cvta_generic_to_shared(&s_mbar);

    if (tid == 0)
        asm volatile("mbarrier.init.shared.b64 [%0], 1;" :: "r"(mbar_a) : "memory");
    __syncthreads();
    // Peer mbarrier must be live before any multicast targets it (done early
    // so it doesn't serialize anything later).
    asm volatile("barrier.cluster.arrive.aligned;" ::: "memory");
    asm volatile("barrier.cluster.wait.aligned;"   ::: "memory");

    // ---- Prefetch edge stream into registers (overlaps the proj phase) ----
    const int t0     = blockIdx.x * THREADS + tid;
    const int stride = gridDim.x * THREADS;
    int2 sv[MAX_SLOTS], dv[MAX_SLOTS]; float2 wv[MAX_SLOTS];
    #pragma unroll
    for (int s = 0; s < MAX_SLOTS; s++) {
        const int t = t0 + s * stride;
        if (t < EDGE_UNITS) {
            sv[s] = reinterpret_cast<const int2*>(edge_index)[t];
            dv[s] = reinterpret_cast<const int2*>(edge_index + N_EDGES)[t];
            wv[s] = reinterpret_cast<const float2*>(edge_weight)[t];
        }
    }
    const float bias = b[0];

    // ---- Proj phase: grid-stride, 4 nodes per warp per iteration ----
    {
        const float4 wa = reinterpret_cast<const float4*>(W)[lane];
        const float4 wb = reinterpret_cast<const float4*>(W + IN_DIM)[lane];
        const int nwarps      = gridDim.x * (THREADS / 32);
        const int warp_global = blockIdx.x * (THREADS / 32) + wid;

        for (int g = warp_global; g < NG4; g += nwarps) {
            const int base = g * 4;
            float4 xv[4];
            #pragma unroll
            for (int i = 0; i < 4; i++)
                xv[i] = reinterpret_cast<const float4*>(x + (size_t)(base + i) * IN_DIM)[lane];

            float sa[4], sb[4];
            #pragma unroll
            for (int i = 0; i < 4; i++) {
                sa[i] = xv[i].x * wa.x + xv[i].y * wa.y + xv[i].z * wa.z + xv[i].w * wa.w;
                sb[i] = xv[i].x * wb.x + xv[i].y * wb.y + xv[i].z * wb.z + xv[i].w * wb.w;
            }
            #pragma unroll
            for (int off = 16; off > 0; off >>= 1) {
                #pragma unroll
                for (int i = 0; i < 4; i++) {
                    sa[i] += __shfl_xor_sync(0xFFFFFFFFu, sa[i], off);
                    sb[i] += __shfl_xor_sync(0xFFFFFFFFu, sb[i], off);
                }
            }
            if (lane == 0) {
                __half2 p[4];
                #pragma unroll
                for (int i = 0; i < 4; i++) p[i] = __floats2half2_rn(sa[i], sb[i]);
                *reinterpret_cast<uint4*>(g_pair + base) = *reinterpret_cast<uint4*>(p);
            }
        }
    }

    // ---- Software grid barrier (all CTAs resident: 1 CTA/SM by smem) ----
    __threadfence();        // each thread's g_pair stores -> GPU-visible
    __syncthreads();        // all threads' fences done before tid0 arrives
    if (tid == 0) {
        const unsigned gen = *(volatile unsigned*)&g_gen;
        if (atomicAdd(&g_cnt, 1) == gridDim.x - 1) {
            g_cnt = 0;                       // reset for next launch/replay
            __threadfence();
            atomicAdd(&g_gen, 1);            // release
        } else {
            while (*(volatile unsigned*)&g_gen == gen) { }
        }
        __threadfence();

        // ---- Stage table: each rank multicasts its half to both CTAs ----
        asm volatile("fence.proxy.async;" ::: "memory");
        asm volatile("mbarrier.arrive.expect_tx.shared.b64 _, [%0], %1;"
                     :: "r"(mbar_a), "r"((uint32_t)TABLE_BYTES) : "memory");
        uint32_t rank;
        asm("mov.u32 %0, %%cluster_ctarank;" : "=r"(rank));
        const uint32_t s_dst = (uint32_t)__cvta_generic_to_shared(s_tab) + rank * CHUNK_BYTES;
        const char*    g_src = reinterpret_cast<const char*>(g_pair) + rank * CHUNK_BYTES;
        asm volatile(
            "cp.async.bulk.shared::cluster.global.mbarrier::complete_tx::bytes"
            ".multicast::cluster [%0], [%1], %2, [%3], %4;"
            :: "r"(s_dst), "l"(g_src), "r"((uint32_t)CHUNK_BYTES),
               "r"(mbar_a), "h"((uint16_t)0x3) : "memory");
    }

    // ---- Wait for the table (acquire orders the LDS gathers) ----
    {
        uint32_t done;
        asm volatile(
            "{\n\t.reg .pred p;\n\t"
            "mbarrier.try_wait.parity.acquire.cta.shared::cta.b64 p, [%1], 0;\n\t"
            "selp.b32 %0, 1, 0, p;\n\t}"
            : "=r"(done) : "r"(mbar_a) : "memory");
        while (!done) {
            asm volatile(
                "{\n\t.reg .pred p;\n\t"
                "mbarrier.try_wait.parity.acquire.cta.shared::cta.b64 p, [%1], 0, 0x989680;\n\t"
                "selp.b32 %0, 1, 0, p;\n\t}"
                : "=r"(done) : "r"(mbar_a) : "memory");
        }
    }

    // ---- Gather + sigmoid + scale (operands already in regs/smem) ----
    #pragma unroll
    for (int s = 0; s < MAX_SLOTS; s++) {
        const int t = t0 + s * stride;
        if (t < EDGE_UNITS) {
            const int i0 = min(max(sv[s].x, 0), N_NODES - 1);
            const int i1 = min(max(sv[s].y, 0), N_NODES - 1);
            const int j0 = min(max(dv[s].x, 0), N_NODES - 1);
            const int j1 = min(max(dv[s].y, 0), N_NODES - 1);

            const float ps0 = __low2float(s_tab[i0]),  ps1 = __low2float(s_tab[i1]);
            const float pd0 = __high2float(s_tab[j0]), pd1 = __high2float(s_tab[j1]);

            float2 r;
            r.x = wv[s].x * sigmoid_tanh(ps0 + pd0 + bias);
            r.y = wv[s].y * sigmoid_tanh(ps1 + pd1 + bias);
            reinterpret_cast<float2*>(out)[t] = r;
        }
    }

    // No CTA exits while a peer's multicast into its SMEM may be in flight.
    asm volatile("barrier.cluster.arrive.aligned;" ::: "memory");
    asm volatile("barrier.cluster.wait.aligned;"   ::: "memory");
}

// ---------------------------------------------------------------------------
// Launch. Inputs (metadata order): x, edge_index, edge_weight, W, b.
// ---------------------------------------------------------------------------
extern "C" void kernel_launch(void* const* d_in, const int* in_sizes, int n_in,
                              void* d_out, int out_size) {
    const float* x  = (const float*)d_in[0];
    const int*   ei = (const int*)d_in[1];
    const float* ew = (const float*)d_in[2];
    const float* W  = (const float*)d_in[3];
    const float* b  = (const float*)d_in[4];
    float*       o  = (float*)d_out;

    cudaFuncSetAttribute(fused_kernel,
                         cudaFuncAttributeMaxDynamicSharedMemorySize, TABLE_BYTES);

    // grid = #SMs rounded down to even (cluster 2); 195KB smem -> 1 CTA/SM,
    // so every CTA is resident and the software grid barrier cannot deadlock.
    int dev = 0, sms = 148;
    cudaGetDevice(&dev);
    cudaDeviceGetAttribute(&sms, cudaDevAttrMultiProcessorCount, dev);
    const int grid = sms & ~1;   // >=82 required for MAX_SLOTS=3; real HW ~148

    fused_kernel<<<grid, THREADS, TABLE_BYTES>>>(x, ei, ew, W, b, o);
}

// round 14
// speedup vs baseline: 1.3377x; 1.3377x over previous
#include <cuda_runtime.h>
#include <cuda_fp16.h>
#include <stdint.h>

#define N_NODES     50000
#define IN_DIM      128
#define N_EDGES     500000
#define EDGE_UNITS  (N_EDGES / 2)          // 250000 int2-edge units
#define NG4         (N_NODES / 4)          // 12500 groups of 4 nodes
#define PROJ_THREADS 1024
#define EDGE_CTAS    96
#define EDGE_THREADS 1024
#define EDGE_SLOTS   3                     // 3*98304 >= 250000
#define TABLE_BYTES  (N_NODES * 4)         // 195.3 KB of half2 pairs
#define TABLE_VEC16  (TABLE_BYTES / 16)    // 12500 16B chunks

// Packed per-node projections: g_pair[n] = (proj_src[n], proj_dst[n]) as half2.
__device__ __half2 g_pair[N_NODES];

// ---------------------------------------------------------------------------
// Kernel 1: persistent node projection (1 wave of CTAs). Triggers PDL at
// entry so the edge kernel can launch and prefetch its stream CONCURRENTLY.
// Grid-stride, 4 nodes/warp; half2-packed 16B stores.
// ---------------------------------------------------------------------------
__global__ __launch_bounds__(PROJ_THREADS, 1)
void proj_kernel(const float* __restrict__ x, const float* __restrict__ W) {
    cudaTriggerProgrammaticLaunchCompletion();   // let the edge kernel start

    const int tid  = threadIdx.x;
    const int wid  = tid >> 5;
    const int lane = tid & 31;
    const int nwarps      = gridDim.x * (PROJ_THREADS / 32);
    const int warp_global = blockIdx.x * (PROJ_THREADS / 32) + wid;

    const float4 wa = reinterpret_cast<const float4*>(W)[lane];            // W[:128]
    const float4 wb = reinterpret_cast<const float4*>(W + IN_DIM)[lane];   // W[128:]

    for (int g = warp_global; g < NG4; g += nwarps) {
        const int base = g * 4;
        float4 xv[4];
        #pragma unroll
        for (int i = 0; i < 4; i++)
            xv[i] = reinterpret_cast<const float4*>(x + (size_t)(base + i) * IN_DIM)[lane];

        float sa[4], sb[4];
        #pragma unroll
        for (int i = 0; i < 4; i++) {
            sa[i] = xv[i].x * wa.x + xv[i].y * wa.y + xv[i].z * wa.z + xv[i].w * wa.w;
            sb[i] = xv[i].x * wb.x + xv[i].y * wb.y + xv[i].z * wb.z + xv[i].w * wb.w;
        }
        #pragma unroll
        for (int off = 16; off > 0; off >>= 1) {
            #pragma unroll
            for (int i = 0; i < 4; i++) {
                sa[i] += __shfl_xor_sync(0xFFFFFFFFu, sa[i], off);
                sb[i] += __shfl_xor_sync(0xFFFFFFFFu, sb[i], off);
            }
        }
        if (lane == 0) {
            __half2 p[4];
            #pragma unroll
            for (int i = 0; i < 4; i++) p[i] = __floats2half2_rn(sa[i], sb[i]);
            *reinterpret_cast<uint4*>(g_pair + base) = *reinterpret_cast<uint4*>(p);
        }
    }
}

// ---------------------------------------------------------------------------
// Sigmoid with one MUFU op: sigmoid(x) = 0.5*tanh(x/2) + 0.5
// ---------------------------------------------------------------------------
__device__ __forceinline__ float sigmoid_tanh(float v) {
    float t;
    asm("tanh.approx.f32 %0, %1;" : "=f"(t) : "f"(0.5f * v));
    return fmaf(0.5f, t, 0.5f);
}

__device__ __forceinline__ void cp_async16(uint32_t smem_dst, const void* gmem_src) {
    asm volatile("cp.async.cg.shared.global [%0], [%1], 16;"
                 :: "r"(smem_dst), "l"(gmem_src));
}

// ---------------------------------------------------------------------------
// Kernel 2 (PDL secondary): starts while proj runs. Prefetches the whole
// edge stream into registers FIRST (overlaps proj), then
// cudaGridDependencySynchronize() (proj's g_pair now visible), then stages
// the 195KB table into smem via cp.async, then LDS gathers + tanh + STG.
// Without PDL support this degrades to stream-ordered = exact R8 behavior.
// ---------------------------------------------------------------------------
__global__ __launch_bounds__(EDGE_THREADS, 1)
void edge_kernel(const int* __restrict__ edge_index,
                 const float* __restrict__ edge_weight,
                 const float* __restrict__ b,
                 float* __restrict__ out) {
    extern __shared__ __half2 s_tab[];   // 195.3 KB table

    const int tid = threadIdx.x;

    // --- Independent work: prefetch edge stream (concurrent with proj) ---
    const int t0     = blockIdx.x * EDGE_THREADS + tid;
    const int stride = EDGE_CTAS * EDGE_THREADS;          // 98304
    int2 sv[EDGE_SLOTS], dv[EDGE_SLOTS]; float2 wv[EDGE_SLOTS];
    #pragma unroll
    for (int s = 0; s < EDGE_SLOTS; s++) {
        const int t = t0 + s * stride;
        if (t < EDGE_UNITS) {
            sv[s] = reinterpret_cast<const int2*>(edge_index)[t];
            dv[s] = reinterpret_cast<const int2*>(edge_index + N_EDGES)[t];
            wv[s] = reinterpret_cast<const float2*>(edge_weight)[t];
        }
    }
    const float bias = b[0];

    // --- Dependency point: proj's g_pair writes must be visible ---
    cudaGridDependencySynchronize();

    // --- Stage the table: 12500 x cp.async.cg 16B, fully coalesced ---
    {
        uint32_t s_base = (uint32_t)__cvta_generic_to_shared(s_tab);
        const char* g_base = reinterpret_cast<const char*>(g_pair);
        for (int i = tid; i < TABLE_VEC16; i += EDGE_THREADS)
            cp_async16(s_base + i * 16, g_base + i * 16);
        asm volatile("cp.async.commit_group;");
        asm volatile("cp.async.wait_group 0;");
    }
    __syncthreads();

    // --- Gather + sigmoid + scale (operands already in regs/smem) ---
    #pragma unroll
    for (int s = 0; s < EDGE_SLOTS; s++) {
        const int t = t0 + s * stride;
        if (t < EDGE_UNITS) {
            const int i0 = min(max(sv[s].x, 0), N_NODES - 1);
            const int i1 = min(max(sv[s].y, 0), N_NODES - 1);
            const int j0 = min(max(dv[s].x, 0), N_NODES - 1);
            const int j1 = min(max(dv[s].y, 0), N_NODES - 1);

            const float ps0 = __low2float(s_tab[i0]),  ps1 = __low2float(s_tab[i1]);
            const float pd0 = __high2float(s_tab[j0]), pd1 = __high2float(s_tab[j1]);

            float2 r;
            r.x = wv[s].x * sigmoid_tanh(ps0 + pd0 + bias);
            r.y = wv[s].y * sigmoid_tanh(ps1 + pd1 + bias);
            reinterpret_cast<float2*>(out)[t] = r;
        }
    }
}

// ---------------------------------------------------------------------------
// Launch. Inputs (metadata order): x, edge_index, edge_weight, W, b.
// proj: normal launch, 1 wave (grid = #SMs). edge: PDL secondary.
// ---------------------------------------------------------------------------
extern "C" void kernel_launch(void* const* d_in, const int* in_sizes, int n_in,
                              void* d_out, int out_size) {
    const float* x  = (const float*)d_in[0];
    const int*   ei = (const int*)d_in[1];
    const float* ew = (const float*)d_in[2];
    const float* W  = (const float*)d_in[3];
    const float* b  = (const float*)d_in[4];
    float*       o  = (float*)d_out;

    cudaFuncSetAttribute(edge_kernel,
                         cudaFuncAttributeMaxDynamicSharedMemorySize, TABLE_BYTES);

    int dev = 0, sms = 148;
    cudaGetDevice(&dev);
    cudaDeviceGetAttribute(&sms, cudaDevAttrMultiProcessorCount, dev);

    // Kernel 1: persistent proj, one wave
    proj_kernel<<<sms, PROJ_THREADS>>>(x, W);

    // Kernel 2: PDL secondary — may start while proj is still running
    {
        cudaLaunchConfig_t cfg = {};
        cfg.gridDim        = dim3(EDGE_CTAS, 1, 1);
        cfg.blockDim       = dim3(EDGE_THREADS, 1, 1);
        cfg.dynamicSmemBytes = TABLE_BYTES;
        cfg.stream         = 0;   // legacy default stream (capture stream)
        cudaLaunchAttribute at[1];
        at[0].id = cudaLaunchAttributeProgrammaticStreamSerialization;
        at[0].val.programmaticStreamSerializationAllowed = 1;
        cfg.attrs    = at;
        cfg.numAttrs = 1;
        cudaLaunchKernelEx(&cfg, edge_kernel, ei, ew, b, o);
    }
}